// round 16
// baseline (speedup 1.0000x reference)
#include <cuda_runtime.h>
#include <cuda_bf16.h>
#include <cstddef>

// Problem constants (fixed shapes for this dataset)
#define NMAX 20000
#define EMAX 320000
#define LL   4

// ---------------- scratch (device globals; no allocation allowed) ----------------
__device__ float  g_x[NMAX * 256];          // node projection [N, H*C]
__device__ float  g_nf[NMAX * 64];          // current node feats (pre-relu of this layer)
__device__ float  g_ef[EMAX * 64];          // current edge feats
__device__ float  g_h[(size_t)EMAX * 192];  // edge MLP hidden
__device__ float  g_asrc[NMAX * 4];
__device__ float  g_adst[NMAX * 4];
__device__ float4 g_raw[EMAX];              // raw (leaky) attention logits per edge [4 heads]
__device__ float4 g_aln[EMAX];              // normalized alpha
__device__ float4 g_m[NMAX];                // per-node per-head max
__device__ float4 g_invd[NMAX];             // per-node per-head 1/denom
__device__ float  g_medge[64 * 4];          // folded edge-attention matrix
__device__ int    g_cnt[NMAX];              // histogram, then cursor
__device__ int    g_rowptr[NMAX + 1];
__device__ int    g_eid[EMAX];              // edge ids sorted by dst (CSR)

// ---------------- helpers ----------------
__device__ __forceinline__ float wsum(float v) {
    #pragma unroll
    for (int o = 16; o > 0; o >>= 1) v += __shfl_xor_sync(0xffffffffu, v, o);
    return v;
}
__device__ __forceinline__ float wmax(float v) {
    #pragma unroll
    for (int o = 16; o > 0; o >>= 1) v = fmaxf(v, __shfl_xor_sync(0xffffffffu, v, o));
    return v;
}

// ---------------- CSR build ----------------
__global__ void k_zero(int N) {
    int i = blockIdx.x * blockDim.x + threadIdx.x;
    if (i < N) g_cnt[i] = 0;
}
__global__ void k_count(const int* __restrict__ dst, int E) {
    int e = blockIdx.x * blockDim.x + threadIdx.x;
    if (e < E) atomicAdd(&g_cnt[dst[e]], 1);
}
// single block, 256 threads: exclusive scan of g_cnt -> g_rowptr, cursor init
__global__ void k_scan(int N) {
    __shared__ int bs[256];
    int t = threadIdx.x;
    int chunk = (N + 255) / 256;
    int s = t * chunk;
    int epos = min(s + chunk, N);
    int loc = 0;
    for (int i = s; i < epos; i++) loc += g_cnt[i];
    bs[t] = loc; __syncthreads();
    for (int off = 1; off < 256; off <<= 1) {
        int v = (t >= off) ? bs[t - off] : 0;
        __syncthreads();
        bs[t] += v;
        __syncthreads();
    }
    int run = bs[t] - loc;  // exclusive prefix
    for (int i = s; i < epos; i++) {
        int c = g_cnt[i];
        g_rowptr[i] = run;
        g_cnt[i] = run;      // cursor
        run += c;
    }
    if (t == 255) g_rowptr[N] = run;
}
__global__ void k_fill(const int* __restrict__ dst, int E) {
    int e = blockIdx.x * blockDim.x + threadIdx.x;
    if (e < E) {
        int pos = atomicAdd(&g_cnt[dst[e]], 1);
        g_eid[pos] = e;
    }
}
__global__ void k_copyef(const float* __restrict__ ef, int total) {
    int i = blockIdx.x * blockDim.x + threadIdx.x;
    if (i < total) g_ef[i] = ef[i];
}

// ---------------- folded edge-attention matrix ----------------
// g_medge[d*4+h] = sum_c W_edge[d, h*64+c] * att_edge[h, c]
__global__ void k_medge(const float* __restrict__ We, const float* __restrict__ attE) {
    int t = threadIdx.x;       // 256 threads
    int d = t >> 2, h = t & 3;
    float s = 0.f;
    #pragma unroll 8
    for (int c = 0; c < 64; c++) s += We[d * 256 + h * 64 + c] * attE[h * 64 + c];
    g_medge[d * 4 + h] = s;
}

// ---------------- node projection: g_x = act(nf) @ W_lin[l] ----------------
__global__ void __launch_bounds__(256) k_proj(const float* __restrict__ nf_ext,
                                              const float* __restrict__ Wl,
                                              int N, int mode /*0: ext no relu, 1: g_nf with relu*/) {
    __shared__ float As[16 * 64];
    int t = threadIdx.x;
    int row0 = blockIdx.x * 16;
    for (int i = t; i < 1024; i += 256) {
        int r = i >> 6, c = i & 63;
        int n = row0 + r;
        float v = 0.f;
        if (n < N) v = mode ? g_nf[n * 64 + c] : nf_ext[n * 64 + c];
        if (mode) v = fmaxf(v, 0.f);
        As[i] = v;
    }
    __syncthreads();
    float acc[16];
    #pragma unroll
    for (int r = 0; r < 16; r++) acc[r] = 0.f;
    for (int k = 0; k < 64; k++) {
        float w = Wl[k * 256 + t];
        #pragma unroll
        for (int r = 0; r < 16; r++) acc[r] += As[r * 64 + k] * w;
    }
    #pragma unroll
    for (int r = 0; r < 16; r++) {
        int n = row0 + r;
        if (n < N) g_x[n * 256 + t] = acc[r];
    }
}

// ---------------- per-node attention logit parts ----------------
__global__ void k_asrcdst(const float* __restrict__ attS, const float* __restrict__ attD, int N) {
    int warp = threadIdx.x >> 5, lane = threadIdx.x & 31;
    int n = blockIdx.x * 8 + warp;
    if (n >= N) return;
    #pragma unroll
    for (int h = 0; h < 4; h++) {
        float x0 = g_x[n * 256 + h * 64 + lane];
        float x1 = g_x[n * 256 + h * 64 + 32 + lane];
        float as = x0 * attS[h * 64 + lane] + x1 * attS[h * 64 + 32 + lane];
        float ad = x0 * attD[h * 64 + lane] + x1 * attD[h * 64 + 32 + lane];
        as = wsum(as);
        ad = wsum(ad);
        if (lane == 0) {
            g_asrc[n * 4 + h] = as;
            g_adst[n * 4 + h] = ad;
        }
    }
}

// ---------------- raw logits per edge (includes leaky relu) ----------------
__global__ void __launch_bounds__(256) k_alpha(const int* __restrict__ src,
                                               const int* __restrict__ dst, int E) {
    __shared__ float Es[64 * 65];
    __shared__ float Ms[256];
    int t = threadIdx.x;
    int e0 = blockIdx.x * 64;
    Ms[t] = g_medge[t];
    for (int i = t; i < 4096; i += 256) {
        int r = i >> 6, c = i & 63;
        int e = e0 + r;
        Es[r * 65 + c] = (e < E) ? g_ef[(size_t)e * 64 + c] : 0.f;
    }
    __syncthreads();
    int el = t >> 2, h = t & 3;
    int e = e0 + el;
    if (e < E) {
        float s = 0.f;
        #pragma unroll 8
        for (int c = 0; c < 64; c++) s += Es[el * 65 + c] * Ms[c * 4 + h];
        float v = s + g_asrc[src[e] * 4 + h] + g_adst[dst[e] * 4 + h];
        v = (v > 0.f) ? v : 0.2f * v;  // leaky relu
        ((float*)g_raw)[e * 4 + h] = v;
    }
}

// ---------------- per-node softmax stats via CSR ----------------
__global__ void k_stats(int N) {
    int warp = threadIdx.x >> 5, lane = threadIdx.x & 31;
    int n = blockIdx.x * 8 + warp;
    if (n >= N) return;
    int beg = g_rowptr[n], end = g_rowptr[n + 1];
    float m0 = -1e30f, m1 = -1e30f, m2 = -1e30f, m3 = -1e30f;
    for (int i = beg + lane; i < end; i += 32) {
        float4 r4 = g_raw[g_eid[i]];
        m0 = fmaxf(m0, r4.x); m1 = fmaxf(m1, r4.y);
        m2 = fmaxf(m2, r4.z); m3 = fmaxf(m3, r4.w);
    }
    m0 = wmax(m0); m1 = wmax(m1); m2 = wmax(m2); m3 = wmax(m3);
    float s0 = 0.f, s1 = 0.f, s2 = 0.f, s3 = 0.f;
    for (int i = beg + lane; i < end; i += 32) {
        float4 r4 = g_raw[g_eid[i]];
        s0 += expf(r4.x - m0); s1 += expf(r4.y - m1);
        s2 += expf(r4.z - m2); s3 += expf(r4.w - m3);
    }
    s0 = wsum(s0); s1 = wsum(s1); s2 = wsum(s2); s3 = wsum(s3);
    if (lane == 0) {
        g_m[n] = make_float4(m0, m1, m2, m3);
        g_invd[n] = make_float4(1.f / (s0 + 1e-16f), 1.f / (s1 + 1e-16f),
                                1.f / (s2 + 1e-16f), 1.f / (s3 + 1e-16f));
    }
}

// ---------------- normalized alpha per edge ----------------
__global__ void k_norm(const int* __restrict__ dst, int E) {
    int e = blockIdx.x * blockDim.x + threadIdx.x;
    if (e >= E) return;
    float4 r4 = g_raw[e];
    int d = dst[e];
    float4 m = g_m[d];
    float4 id = g_invd[d];
    float4 o;
    o.x = expf(r4.x - m.x) * id.x;
    o.y = expf(r4.y - m.y) * id.y;
    o.z = expf(r4.z - m.z) * id.z;
    o.w = expf(r4.w - m.w) * id.w;
    g_aln[e] = o;
}

// ---------------- aggregation + head-mean + bias + LayerNorm -> g_nf ----------------
__global__ void k_agg(const int* __restrict__ src, const float* __restrict__ bias,
                      const float* __restrict__ lng, const float* __restrict__ lnb, int N) {
    int warp = threadIdx.x >> 5, lane = threadIdx.x & 31;
    int n = blockIdx.x * 8 + warp;
    if (n >= N) return;
    int beg = g_rowptr[n], end = g_rowptr[n + 1];
    float a00 = 0, a01 = 0, a02 = 0, a03 = 0;
    float a10 = 0, a11 = 0, a12 = 0, a13 = 0;
    for (int i = beg; i < end; i++) {
        int e = g_eid[i];
        int s = src[e];
        float4 a = g_aln[e];
        const float* xp = &g_x[s * 256];
        a00 += a.x * xp[lane];        a10 += a.x * xp[32 + lane];
        a01 += a.y * xp[64 + lane];   a11 += a.y * xp[96 + lane];
        a02 += a.z * xp[128 + lane];  a12 += a.z * xp[160 + lane];
        a03 += a.w * xp[192 + lane];  a13 += a.w * xp[224 + lane];
    }
    float o0 = (a00 + a01 + a02 + a03) * 0.25f + bias[lane];
    float o1 = (a10 + a11 + a12 + a13) * 0.25f + bias[32 + lane];
    float mu = wsum(o0 + o1) * (1.f / 64.f);
    float d0 = o0 - mu, d1 = o1 - mu;
    float var = wsum(d0 * d0 + d1 * d1) * (1.f / 64.f);
    float rstd = rsqrtf(var + 1e-5f);
    g_nf[n * 64 + lane]      = d0 * rstd * lng[lane]      + lnb[lane];
    g_nf[n * 64 + 32 + lane] = d1 * rstd * lng[32 + lane] + lnb[32 + lane];
}

// ---------------- edge MLP stage 1: h = relu(LN(A @ eW1 + b1)) ----------------
// A = [ni+nj, |ni-nj|, ef]  (built in smem, transposed, per 32-edge tile)
__global__ void __launch_bounds__(192) k_eu1(const int* __restrict__ src, const int* __restrict__ dst,
                                             const float* __restrict__ W1, const float* __restrict__ b1,
                                             const float* __restrict__ lng, const float* __restrict__ lnb,
                                             int E) {
    __shared__ float AsT[192 * 33];
    __shared__ int ss[32], dd[32];
    __shared__ float red[32 * 48];
    __shared__ float mus[32], rst[32];
    int t = threadIdx.x;
    int e0 = blockIdx.x * 32;
    if (t < 32) {
        int e = e0 + t;
        ss[t] = (e < E) ? src[e] : 0;
        dd[t] = (e < E) ? dst[e] : 0;
    }
    __syncthreads();
    for (int i = t; i < 2048; i += 192) {
        int r = i >> 6, c = i & 63;
        int e = e0 + r;
        float ni = 0.f, nj = 0.f, ef = 0.f;
        if (e < E) {
            ni = g_nf[ss[r] * 64 + c];
            nj = g_nf[dd[r] * 64 + c];
            ef = g_ef[(size_t)e * 64 + c];
        }
        AsT[c * 33 + r] = ni + nj;
        AsT[(64 + c) * 33 + r] = fabsf(ni - nj);
        AsT[(128 + c) * 33 + r] = ef;
    }
    __syncthreads();
    int cg = t % 48;      // cols cg*4 .. cg*4+3
    int rs = t / 48;      // rows rs*8 .. rs*8+7
    float acc[8][4];
    #pragma unroll
    for (int r = 0; r < 8; r++)
        #pragma unroll
        for (int c = 0; c < 4; c++) acc[r][c] = 0.f;

    for (int k = 0; k < 192; k++) {
        float4 w = *reinterpret_cast<const float4*>(W1 + k * 192 + (cg << 2));
        const float* ap = &AsT[k * 33 + (rs << 3)];
        #pragma unroll
        for (int r = 0; r < 8; r++) {
            float a = ap[r];
            acc[r][0] += a * w.x; acc[r][1] += a * w.y;
            acc[r][2] += a * w.z; acc[r][3] += a * w.w;
        }
    }
    float4 bv = *reinterpret_cast<const float4*>(b1 + (cg << 2));
    #pragma unroll
    for (int r = 0; r < 8; r++) {
        acc[r][0] += bv.x; acc[r][1] += bv.y; acc[r][2] += bv.z; acc[r][3] += bv.w;
    }
    // mean over 192
    #pragma unroll
    for (int r = 0; r < 8; r++)
        red[(rs * 8 + r) * 48 + cg] = acc[r][0] + acc[r][1] + acc[r][2] + acc[r][3];
    __syncthreads();
    if (t < 32) {
        float s = 0.f;
        #pragma unroll 8
        for (int j = 0; j < 48; j++) s += red[t * 48 + j];
        mus[t] = s * (1.f / 192.f);
    }
    __syncthreads();
    // centered variance
    #pragma unroll
    for (int r = 0; r < 8; r++) {
        float mu = mus[rs * 8 + r];
        float q = 0.f;
        #pragma unroll
        for (int c = 0; c < 4; c++) { float dv = acc[r][c] - mu; q += dv * dv; }
        red[(rs * 8 + r) * 48 + cg] = q;
    }
    __syncthreads();
    if (t < 32) {
        float s = 0.f;
        #pragma unroll 8
        for (int j = 0; j < 48; j++) s += red[t * 48 + j];
        rst[t] = rsqrtf(s * (1.f / 192.f) + 1e-5f);
    }
    __syncthreads();
    float4 gv = *reinterpret_cast<const float4*>(lng + (cg << 2));
    float4 bw = *reinterpret_cast<const float4*>(lnb + (cg << 2));
    #pragma unroll
    for (int r = 0; r < 8; r++) {
        int row = rs * 8 + r;
        int e = e0 + row;
        if (e < E) {
            float mu = mus[row], rr = rst[row];
            float4 o;
            o.x = fmaxf((acc[r][0] - mu) * rr * gv.x + bw.x, 0.f);
            o.y = fmaxf((acc[r][1] - mu) * rr * gv.y + bw.y, 0.f);
            o.z = fmaxf((acc[r][2] - mu) * rr * gv.z + bw.z, 0.f);
            o.w = fmaxf((acc[r][3] - mu) * rr * gv.w + bw.w, 0.f);
            *reinterpret_cast<float4*>(&g_h[(size_t)e * 192 + (cg << 2)]) = o;
        }
    }
}

// ---------------- edge MLP stage 2: ef = h @ eW2 + b2 + ef ----------------
__global__ void __launch_bounds__(128) k_eu2(const float* __restrict__ W2, const float* __restrict__ b2,
                                             int E) {
    __shared__ float Hs[32 * 65];
    int t = threadIdx.x;
    int e0 = blockIdx.x * 64;
    int cg = t & 15;   // cols cg*4..+3
    int rs = t >> 4;   // rows rs*8..+7 (8 groups x 8 = 64 rows)
    float acc[8][4];
    #pragma unroll
    for (int r = 0; r < 8; r++)
        #pragma unroll
        for (int c = 0; c < 4; c++) acc[r][c] = 0.f;

    for (int kc = 0; kc < 192; kc += 32) {
        __syncthreads();
        for (int i = t; i < 2048; i += 128) {
            int r = i >> 5, k = i & 31;
            int e = e0 + r;
            Hs[k * 65 + r] = (e < E) ? g_h[(size_t)e * 192 + kc + k] : 0.f;
        }
        __syncthreads();
        #pragma unroll 4
        for (int k = 0; k < 32; k++) {
            float4 w = *reinterpret_cast<const float4*>(W2 + (kc + k) * 64 + (cg << 2));
            const float* hp = &Hs[k * 65 + (rs << 3)];
            #pragma unroll
            for (int r = 0; r < 8; r++) {
                float a = hp[r];
                acc[r][0] += a * w.x; acc[r][1] += a * w.y;
                acc[r][2] += a * w.z; acc[r][3] += a * w.w;
            }
        }
    }
    float4 bv = *reinterpret_cast<const float4*>(b2 + (cg << 2));
    #pragma unroll
    for (int r = 0; r < 8; r++) {
        int e = e0 + rs * 8 + r;
        if (e < E) {
            float4 res = *reinterpret_cast<const float4*>(&g_ef[(size_t)e * 64 + (cg << 2)]);
            float4 o;
            o.x = acc[r][0] + bv.x + res.x;
            o.y = acc[r][1] + bv.y + res.y;
            o.z = acc[r][2] + bv.z + res.z;
            o.w = acc[r][3] + bv.w + res.w;
            *reinterpret_cast<float4*>(&g_ef[(size_t)e * 64 + (cg << 2)]) = o;
        }
    }
}

// ---------------- final output: [node_feats | edge_feats] ----------------
__global__ void k_output(float* __restrict__ out, int nElems, int eElems) {
    int total = nElems + eElems;
    for (int i = blockIdx.x * blockDim.x + threadIdx.x; i < total; i += gridDim.x * blockDim.x) {
        out[i] = (i < nElems) ? g_nf[i] : g_ef[i - nElems];
    }
}

// ---------------- launch ----------------
extern "C" void kernel_launch(void* const* d_in, const int* in_sizes, int n_in,
                              void* d_out, int out_size) {
    const float* node      = (const float*)d_in[0];
    const float* edge      = (const float*)d_in[1];
    const int*   eidx      = (const int*)d_in[2];
    const float* W_lin     = (const float*)d_in[3];
    const float* W_edge    = (const float*)d_in[4];
    const float* att_src   = (const float*)d_in[5];
    const float* att_dst   = (const float*)d_in[6];
    const float* att_edge  = (const float*)d_in[7];
    const float* bias_conv = (const float*)d_in[8];
    const float* ln_g      = (const float*)d_in[9];
    const float* ln_b      = (const float*)d_in[10];
    const float* eW1       = (const float*)d_in[11];
    const float* eb1       = (const float*)d_in[12];
    const float* eln_g     = (const float*)d_in[13];
    const float* eln_b     = (const float*)d_in[14];
    const float* eW2       = (const float*)d_in[15];
    const float* eb2       = (const float*)d_in[16];

    int N = in_sizes[0] / 64;
    int E = in_sizes[1] / 64;
    const int* src = eidx;
    const int* dstp = eidx + E;

    // CSR by dst + init edge feature buffer
    k_zero<<<(N + 255) / 256, 256>>>(N);
    k_count<<<(E + 255) / 256, 256>>>(dstp, E);
    k_scan<<<1, 256>>>(N);
    k_fill<<<(E + 255) / 256, 256>>>(dstp, E);
    k_copyef<<<(E * 64 + 255) / 256, 256>>>(edge, E * 64);

    for (int l = 0; l < LL; l++) {
        k_medge<<<1, 256>>>(W_edge + (size_t)l * 64 * 256, att_edge + l * 256);
        k_proj<<<(N + 15) / 16, 256>>>(node, W_lin + (size_t)l * 64 * 256, N, l == 0 ? 0 : 1);
        k_asrcdst<<<(N + 7) / 8, 256>>>(att_src + l * 256, att_dst + l * 256, N);
        k_alpha<<<(E + 63) / 64, 256>>>(src, dstp, E);
        k_stats<<<(N + 7) / 8, 256>>>(N);
        k_norm<<<(E + 255) / 256, 256>>>(dstp, E);
        k_agg<<<(N + 7) / 8, 256>>>(src, bias_conv + l * 64, ln_g + l * 64, ln_b + l * 64, N);
        k_eu1<<<(E + 31) / 32, 192>>>(src, dstp,
                                      eW1 + (size_t)l * 192 * 192, eb1 + l * 192,
                                      eln_g + l * 192, eln_b + l * 192, E);
        k_eu2<<<(E + 63) / 64, 128>>>(eW2 + (size_t)l * 192 * 64, eb2 + l * 64, E);
    }

    k_output<<<4096, 256>>>((float*)d_out, N * 64, E * 64);
}

// round 17
// speedup vs baseline: 1.0011x; 1.0011x over previous
#include <cuda_runtime.h>
#include <cuda_bf16.h>
#include <cstddef>

// Problem constants (fixed shapes for this dataset)
#define NMAX 20000
#define EMAX 320000
#define LL   4

// ---------------- scratch (device globals; no allocation allowed) ----------------
__device__ float  g_x[NMAX * 256];          // node projection [N, H*C]
__device__ float  g_nf[NMAX * 64];          // current node feats (pre-relu of this layer)
__device__ float  g_ef[EMAX * 64];          // current edge feats
__device__ float  g_h[(size_t)EMAX * 192];  // edge MLP hidden
__device__ float  g_asrc[NMAX * 4];
__device__ float  g_adst[NMAX * 4];
__device__ float4 g_raw[EMAX];              // raw (leaky) attention logits per edge [4 heads]
__device__ float4 g_aln[EMAX];              // normalized alpha
__device__ float4 g_m[NMAX];                // per-node per-head max
__device__ float4 g_invd[NMAX];             // per-node per-head 1/denom
__device__ float  g_medge[64 * 4];          // folded edge-attention matrix
__device__ int    g_cnt[NMAX];              // histogram, then cursor
__device__ int    g_rowptr[NMAX + 1];
__device__ int    g_eid[EMAX];              // edge ids sorted by dst (CSR)

// ---------------- helpers ----------------
__device__ __forceinline__ float wsum(float v) {
    #pragma unroll
    for (int o = 16; o > 0; o >>= 1) v += __shfl_xor_sync(0xffffffffu, v, o);
    return v;
}
__device__ __forceinline__ float wmax(float v) {
    #pragma unroll
    for (int o = 16; o > 0; o >>= 1) v = fmaxf(v, __shfl_xor_sync(0xffffffffu, v, o));
    return v;
}

// ---------------- CSR build ----------------
__global__ void k_zero(int N) {
    int i = blockIdx.x * blockDim.x + threadIdx.x;
    if (i < N) g_cnt[i] = 0;
}
__global__ void k_count(const int* __restrict__ dst, int E) {
    int e = blockIdx.x * blockDim.x + threadIdx.x;
    if (e < E) atomicAdd(&g_cnt[dst[e]], 1);
}
// single block, 256 threads: exclusive scan of g_cnt -> g_rowptr, cursor init
__global__ void k_scan(int N) {
    __shared__ int bs[256];
    int t = threadIdx.x;
    int chunk = (N + 255) / 256;
    int s = t * chunk;
    int epos = min(s + chunk, N);
    int loc = 0;
    for (int i = s; i < epos; i++) loc += g_cnt[i];
    bs[t] = loc; __syncthreads();
    for (int off = 1; off < 256; off <<= 1) {
        int v = (t >= off) ? bs[t - off] : 0;
        __syncthreads();
        bs[t] += v;
        __syncthreads();
    }
    int run = bs[t] - loc;  // exclusive prefix
    for (int i = s; i < epos; i++) {
        int c = g_cnt[i];
        g_rowptr[i] = run;
        g_cnt[i] = run;      // cursor
        run += c;
    }
    if (t == 255) g_rowptr[N] = run;
}
__global__ void k_fill(const int* __restrict__ dst, int E) {
    int e = blockIdx.x * blockDim.x + threadIdx.x;
    if (e < E) {
        int pos = atomicAdd(&g_cnt[dst[e]], 1);
        g_eid[pos] = e;
    }
}
__global__ void k_copyef(const float* __restrict__ ef, int total) {
    int i = blockIdx.x * blockDim.x + threadIdx.x;
    if (i < total) g_ef[i] = ef[i];
}

// ---------------- folded edge-attention matrix ----------------
// g_medge[d*4+h] = sum_c W_edge[d, h*64+c] * att_edge[h, c]
__global__ void k_medge(const float* __restrict__ We, const float* __restrict__ attE) {
    int t = threadIdx.x;       // 256 threads
    int d = t >> 2, h = t & 3;
    float s = 0.f;
    #pragma unroll 8
    for (int c = 0; c < 64; c++) s += We[d * 256 + h * 64 + c] * attE[h * 64 + c];
    g_medge[d * 4 + h] = s;
}

// ---------------- node projection: g_x = act(nf) @ W_lin[l] ----------------
__global__ void __launch_bounds__(256) k_proj(const float* __restrict__ nf_ext,
                                              const float* __restrict__ Wl,
                                              int N, int mode /*0: ext no relu, 1: g_nf with relu*/) {
    __shared__ float As[16 * 64];
    int t = threadIdx.x;
    int row0 = blockIdx.x * 16;
    for (int i = t; i < 1024; i += 256) {
        int r = i >> 6, c = i & 63;
        int n = row0 + r;
        float v = 0.f;
        if (n < N) v = mode ? g_nf[n * 64 + c] : nf_ext[n * 64 + c];
        if (mode) v = fmaxf(v, 0.f);
        As[i] = v;
    }
    __syncthreads();
    float acc[16];
    #pragma unroll
    for (int r = 0; r < 16; r++) acc[r] = 0.f;
    for (int k = 0; k < 64; k++) {
        float w = Wl[k * 256 + t];
        #pragma unroll
        for (int r = 0; r < 16; r++) acc[r] += As[r * 64 + k] * w;
    }
    #pragma unroll
    for (int r = 0; r < 16; r++) {
        int n = row0 + r;
        if (n < N) g_x[n * 256 + t] = acc[r];
    }
}

// ---------------- per-node attention logit parts ----------------
__global__ void k_asrcdst(const float* __restrict__ attS, const float* __restrict__ attD, int N) {
    int warp = threadIdx.x >> 5, lane = threadIdx.x & 31;
    int n = blockIdx.x * 8 + warp;
    if (n >= N) return;
    #pragma unroll
    for (int h = 0; h < 4; h++) {
        float x0 = g_x[n * 256 + h * 64 + lane];
        float x1 = g_x[n * 256 + h * 64 + 32 + lane];
        float as = x0 * attS[h * 64 + lane] + x1 * attS[h * 64 + 32 + lane];
        float ad = x0 * attD[h * 64 + lane] + x1 * attD[h * 64 + 32 + lane];
        as = wsum(as);
        ad = wsum(ad);
        if (lane == 0) {
            g_asrc[n * 4 + h] = as;
            g_adst[n * 4 + h] = ad;
        }
    }
}

// ---------------- raw logits per edge (includes leaky relu) ----------------
__global__ void __launch_bounds__(256) k_alpha(const int* __restrict__ src,
                                               const int* __restrict__ dst, int E) {
    __shared__ float Es[64 * 65];
    __shared__ float Ms[256];
    int t = threadIdx.x;
    int e0 = blockIdx.x * 64;
    Ms[t] = g_medge[t];
    for (int i = t; i < 4096; i += 256) {
        int r = i >> 6, c = i & 63;
        int e = e0 + r;
        Es[r * 65 + c] = (e < E) ? g_ef[(size_t)e * 64 + c] : 0.f;
    }
    __syncthreads();
    int el = t >> 2, h = t & 3;
    int e = e0 + el;
    if (e < E) {
        float s = 0.f;
        #pragma unroll 8
        for (int c = 0; c < 64; c++) s += Es[el * 65 + c] * Ms[c * 4 + h];
        float v = s + g_asrc[src[e] * 4 + h] + g_adst[dst[e] * 4 + h];
        v = (v > 0.f) ? v : 0.2f * v;  // leaky relu
        ((float*)g_raw)[e * 4 + h] = v;
    }
}

// ---------------- per-node softmax stats via CSR ----------------
__global__ void k_stats(int N) {
    int warp = threadIdx.x >> 5, lane = threadIdx.x & 31;
    int n = blockIdx.x * 8 + warp;
    if (n >= N) return;
    int beg = g_rowptr[n], end = g_rowptr[n + 1];
    float m0 = -1e30f, m1 = -1e30f, m2 = -1e30f, m3 = -1e30f;
    for (int i = beg + lane; i < end; i += 32) {
        float4 r4 = g_raw[g_eid[i]];
        m0 = fmaxf(m0, r4.x); m1 = fmaxf(m1, r4.y);
        m2 = fmaxf(m2, r4.z); m3 = fmaxf(m3, r4.w);
    }
    m0 = wmax(m0); m1 = wmax(m1); m2 = wmax(m2); m3 = wmax(m3);
    float s0 = 0.f, s1 = 0.f, s2 = 0.f, s3 = 0.f;
    for (int i = beg + lane; i < end; i += 32) {
        float4 r4 = g_raw[g_eid[i]];
        s0 += expf(r4.x - m0); s1 += expf(r4.y - m1);
        s2 += expf(r4.z - m2); s3 += expf(r4.w - m3);
    }
    s0 = wsum(s0); s1 = wsum(s1); s2 = wsum(s2); s3 = wsum(s3);
    if (lane == 0) {
        g_m[n] = make_float4(m0, m1, m2, m3);
        g_invd[n] = make_float4(1.f / (s0 + 1e-16f), 1.f / (s1 + 1e-16f),
                                1.f / (s2 + 1e-16f), 1.f / (s3 + 1e-16f));
    }
}

// ---------------- normalized alpha per edge ----------------
__global__ void k_norm(const int* __restrict__ dst, int E) {
    int e = blockIdx.x * blockDim.x + threadIdx.x;
    if (e >= E) return;
    float4 r4 = g_raw[e];
    int d = dst[e];
    float4 m = g_m[d];
    float4 id = g_invd[d];
    float4 o;
    o.x = expf(r4.x - m.x) * id.x;
    o.y = expf(r4.y - m.y) * id.y;
    o.z = expf(r4.z - m.z) * id.z;
    o.w = expf(r4.w - m.w) * id.w;
    g_aln[e] = o;
}

// ---------------- aggregation + head-mean + bias + LayerNorm -> g_nf ----------------
__global__ void k_agg(const int* __restrict__ src, const float* __restrict__ bias,
                      const float* __restrict__ lng, const float* __restrict__ lnb, int N) {
    int warp = threadIdx.x >> 5, lane = threadIdx.x & 31;
    int n = blockIdx.x * 8 + warp;
    if (n >= N) return;
    int beg = g_rowptr[n], end = g_rowptr[n + 1];
    float a00 = 0, a01 = 0, a02 = 0, a03 = 0;
    float a10 = 0, a11 = 0, a12 = 0, a13 = 0;
    for (int i = beg; i < end; i++) {
        int e = g_eid[i];
        int s = src[e];
        float4 a = g_aln[e];
        const float* xp = &g_x[s * 256];
        a00 += a.x * xp[lane];        a10 += a.x * xp[32 + lane];
        a01 += a.y * xp[64 + lane];   a11 += a.y * xp[96 + lane];
        a02 += a.z * xp[128 + lane];  a12 += a.z * xp[160 + lane];
        a03 += a.w * xp[192 + lane];  a13 += a.w * xp[224 + lane];
    }
    float o0 = (a00 + a01 + a02 + a03) * 0.25f + bias[lane];
    float o1 = (a10 + a11 + a12 + a13) * 0.25f + bias[32 + lane];
    float mu = wsum(o0 + o1) * (1.f / 64.f);
    float d0 = o0 - mu, d1 = o1 - mu;
    float var = wsum(d0 * d0 + d1 * d1) * (1.f / 64.f);
    float rstd = rsqrtf(var + 1e-5f);
    g_nf[n * 64 + lane]      = d0 * rstd * lng[lane]      + lnb[lane];
    g_nf[n * 64 + 32 + lane] = d1 * rstd * lng[32 + lane] + lnb[32 + lane];
}

// ---------------- edge MLP stage 1: h = relu(LN(A @ eW1 + b1)) ----------------
// A = [ni+nj, |ni-nj|, ef]  (built in smem, transposed, per 32-edge tile)
__global__ void __launch_bounds__(192) k_eu1(const int* __restrict__ src, const int* __restrict__ dst,
                                             const float* __restrict__ W1, const float* __restrict__ b1,
                                             const float* __restrict__ lng, const float* __restrict__ lnb,
                                             int E) {
    __shared__ float AsT[192 * 33];
    __shared__ int ss[32], dd[32];
    __shared__ float red[32 * 48];
    __shared__ float mus[32], rst[32];
    int t = threadIdx.x;
    int e0 = blockIdx.x * 32;
    if (t < 32) {
        int e = e0 + t;
        ss[t] = (e < E) ? src[e] : 0;
        dd[t] = (e < E) ? dst[e] : 0;
    }
    __syncthreads();
    for (int i = t; i < 2048; i += 192) {
        int r = i >> 6, c = i & 63;
        int e = e0 + r;
        float ni = 0.f, nj = 0.f, ef = 0.f;
        if (e < E) {
            ni = g_nf[ss[r] * 64 + c];
            nj = g_nf[dd[r] * 64 + c];
            ef = g_ef[(size_t)e * 64 + c];
        }
        AsT[c * 33 + r] = ni + nj;
        AsT[(64 + c) * 33 + r] = fabsf(ni - nj);
        AsT[(128 + c) * 33 + r] = ef;
    }
    __syncthreads();
    int cg = t % 48;      // cols cg*4 .. cg*4+3
    int rs = t / 48;      // rows rs*8 .. rs*8+7
    float acc[8][4];
    #pragma unroll
    for (int r = 0; r < 8; r++)
        #pragma unroll
        for (int c = 0; c < 4; c++) acc[r][c] = 0.f;

    for (int k = 0; k < 192; k++) {
        float4 w = *reinterpret_cast<const float4*>(W1 + k * 192 + (cg << 2));
        const float* ap = &AsT[k * 33 + (rs << 3)];
        #pragma unroll
        for (int r = 0; r < 8; r++) {
            float a = ap[r];
            acc[r][0] += a * w.x; acc[r][1] += a * w.y;
            acc[r][2] += a * w.z; acc[r][3] += a * w.w;
        }
    }
    float4 bv = *reinterpret_cast<const float4*>(b1 + (cg << 2));
    #pragma unroll
    for (int r = 0; r < 8; r++) {
        acc[r][0] += bv.x; acc[r][1] += bv.y; acc[r][2] += bv.z; acc[r][3] += bv.w;
    }
    // mean over 192
    #pragma unroll
    for (int r = 0; r < 8; r++)
        red[(rs * 8 + r) * 48 + cg] = acc[r][0] + acc[r][1] + acc[r][2] + acc[r][3];
    __syncthreads();
    if (t < 32) {
        float s = 0.f;
        #pragma unroll 8
        for (int j = 0; j < 48; j++) s += red[t * 48 + j];
        mus[t] = s * (1.f / 192.f);
    }
    __syncthreads();
    // centered variance
    #pragma unroll
    for (int r = 0; r < 8; r++) {
        float mu = mus[rs * 8 + r];
        float q = 0.f;
        #pragma unroll
        for (int c = 0; c < 4; c++) { float dv = acc[r][c] - mu; q += dv * dv; }
        red[(rs * 8 + r) * 48 + cg] = q;
    }
    __syncthreads();
    if (t < 32) {
        float s = 0.f;
        #pragma unroll 8
        for (int j = 0; j < 48; j++) s += red[t * 48 + j];
        rst[t] = rsqrtf(s * (1.f / 192.f) + 1e-5f);
    }
    __syncthreads();
    float4 gv = *reinterpret_cast<const float4*>(lng + (cg << 2));
    float4 bw = *reinterpret_cast<const float4*>(lnb + (cg << 2));
    #pragma unroll
    for (int r = 0; r < 8; r++) {
        int row = rs * 8 + r;
        int e = e0 + row;
        if (e < E) {
            float mu = mus[row], rr = rst[row];
            float4 o;
            o.x = fmaxf((acc[r][0] - mu) * rr * gv.x + bw.x, 0.f);
            o.y = fmaxf((acc[r][1] - mu) * rr * gv.y + bw.y, 0.f);
            o.z = fmaxf((acc[r][2] - mu) * rr * gv.z + bw.z, 0.f);
            o.w = fmaxf((acc[r][3] - mu) * rr * gv.w + bw.w, 0.f);
            *reinterpret_cast<float4*>(&g_h[(size_t)e * 192 + (cg << 2)]) = o;
        }
    }
}

// ---------------- edge MLP stage 2: ef = h @ eW2 + b2 + ef ----------------
__global__ void __launch_bounds__(128) k_eu2(const float* __restrict__ W2, const float* __restrict__ b2,
                                             int E) {
    __shared__ float Hs[32 * 65];
    int t = threadIdx.x;
    int e0 = blockIdx.x * 64;
    int cg = t & 15;   // cols cg*4..+3
    int rs = t >> 4;   // rows rs*8..+7 (8 groups x 8 = 64 rows)
    float acc[8][4];
    #pragma unroll
    for (int r = 0; r < 8; r++)
        #pragma unroll
        for (int c = 0; c < 4; c++) acc[r][c] = 0.f;

    for (int kc = 0; kc < 192; kc += 32) {
        __syncthreads();
        for (int i = t; i < 2048; i += 128) {
            int r = i >> 5, k = i & 31;
            int e = e0 + r;
            Hs[k * 65 + r] = (e < E) ? g_h[(size_t)e * 192 + kc + k] : 0.f;
        }
        __syncthreads();
        #pragma unroll 4
        for (int k = 0; k < 32; k++) {
            float4 w = *reinterpret_cast<const float4*>(W2 + (kc + k) * 64 + (cg << 2));
            const float* hp = &Hs[k * 65 + (rs << 3)];
            #pragma unroll
            for (int r = 0; r < 8; r++) {
                float a = hp[r];
                acc[r][0] += a * w.x; acc[r][1] += a * w.y;
                acc[r][2] += a * w.z; acc[r][3] += a * w.w;
            }
        }
    }
    float4 bv = *reinterpret_cast<const float4*>(b2 + (cg << 2));
    #pragma unroll
    for (int r = 0; r < 8; r++) {
        int e = e0 + rs * 8 + r;
        if (e < E) {
            float4 res = *reinterpret_cast<const float4*>(&g_ef[(size_t)e * 64 + (cg << 2)]);
            float4 o;
            o.x = acc[r][0] + bv.x + res.x;
            o.y = acc[r][1] + bv.y + res.y;
            o.z = acc[r][2] + bv.z + res.z;
            o.w = acc[r][3] + bv.w + res.w;
            *reinterpret_cast<float4*>(&g_ef[(size_t)e * 64 + (cg << 2)]) = o;
        }
    }
}

// ---------------- final output: [node_feats | edge_feats] ----------------
__global__ void k_output(float* __restrict__ out, int nElems, int eElems) {
    int total = nElems + eElems;
    for (int i = blockIdx.x * blockDim.x + threadIdx.x; i < total; i += gridDim.x * blockDim.x) {
        out[i] = (i < nElems) ? g_nf[i] : g_ef[i - nElems];
    }
}

// ---------------- launch ----------------
extern "C" void kernel_launch(void* const* d_in, const int* in_sizes, int n_in,
                              void* d_out, int out_size) {
    const float* node      = (const float*)d_in[0];
    const float* edge      = (const float*)d_in[1];
    const int*   eidx      = (const int*)d_in[2];
    const float* W_lin     = (const float*)d_in[3];
    const float* W_edge    = (const float*)d_in[4];
    const float* att_src   = (const float*)d_in[5];
    const float* att_dst   = (const float*)d_in[6];
    const float* att_edge  = (const float*)d_in[7];
    const float* bias_conv = (const float*)d_in[8];
    const float* ln_g      = (const float*)d_in[9];
    const float* ln_b      = (const float*)d_in[10];
    const float* eW1       = (const float*)d_in[11];
    const float* eb1       = (const float*)d_in[12];
    const float* eln_g     = (const float*)d_in[13];
    const float* eln_b     = (const float*)d_in[14];
    const float* eW2       = (const float*)d_in[15];
    const float* eb2       = (const float*)d_in[16];

    int N = in_sizes[0] / 64;
    int E = in_sizes[1] / 64;
    const int* src = eidx;
    const int* dstp = eidx + E;

    // CSR by dst + init edge feature buffer
    k_zero<<<(N + 255) / 256, 256>>>(N);
    k_count<<<(E + 255) / 256, 256>>>(dstp, E);
    k_scan<<<1, 256>>>(N);
    k_fill<<<(E + 255) / 256, 256>>>(dstp, E);
    k_copyef<<<(E * 64 + 255) / 256, 256>>>(edge, E * 64);

    for (int l = 0; l < LL; l++) {
        k_medge<<<1, 256>>>(W_edge + (size_t)l * 64 * 256, att_edge + l * 256);
        k_proj<<<(N + 15) / 16, 256>>>(node, W_lin + (size_t)l * 64 * 256, N, l == 0 ? 0 : 1);
        k_asrcdst<<<(N + 7) / 8, 256>>>(att_src + l * 256, att_dst + l * 256, N);
        k_alpha<<<(E + 63) / 64, 256>>>(src, dstp, E);
        k_stats<<<(N + 7) / 8, 256>>>(N);
        k_norm<<<(E + 255) / 256, 256>>>(dstp, E);
        k_agg<<<(N + 7) / 8, 256>>>(src, bias_conv + l * 64, ln_g + l * 64, ln_b + l * 64, N);
        k_eu1<<<(E + 31) / 32, 192>>>(src, dstp,
                                      eW1 + (size_t)l * 192 * 192, eb1 + l * 192,
                                      eln_g + l * 192, eln_b + l * 192, E);
        k_eu2<<<(E + 63) / 64, 128>>>(eW2 + (size_t)l * 192 * 64, eb2 + l * 64, E);
    }

    k_output<<<4096, 256>>>((float*)d_out, N * 64, E * 64);
}